// round 15
// baseline (speedup 1.0000x reference)
#include <cuda_runtime.h>
#include <math.h>
#include <float.h>
#include <stdint.h>

#define NB 4096
#define NC 50257
#define RT 256

// Scratch (no allocations allowed); 16B-aligned for vector loads.
__device__ __align__(16) float g_l[NB];
__device__ __align__(16) int   g_neg[NB];
__device__ unsigned g_done;   // zero-initialized by loader; reset by elected block

__global__ __launch_bounds__(RT)
void npc_fused_kernel(const float* __restrict__ logits,
                      const int* __restrict__ target,
                      float* __restrict__ l_buf,
                      int* __restrict__ neg_buf,
                      float* __restrict__ out)
{
    const int b = blockIdx.x;
    const int tid = threadIdx.x;
    const int lane = tid & 31;
    const int wid = tid >> 5;

    __shared__ float sh_a[8];
    __shared__ float sh_b[8];
    __shared__ float sh_c[8];
    __shared__ int sh_flag;

    // ─────────────── row phase (proven ~6.5 TB/s loop, unchanged) ─────────
    {
        const float* row = logits + (size_t)b * NC;
        const int t = target[b];

        const uintptr_t addr = (uintptr_t)row;
        const int head = ((16 - (int)(addr & 15)) & 15) >> 2;
        const int nvec = (NC - head) >> 2;
        const int tail_start = head + (nvec << 2);

        float m = -FLT_MAX;
        float s0 = 0.0f, s1 = 0.0f, s2 = 0.0f, s3 = 0.0f;

        const float4* v = (const float4*)(row + head);

        const int step = RT * 4;
        const int nmain = nvec - (nvec % step);
        int i = tid;
        for (; i < nmain; i += step) {
            float4 xa = __ldcs(v + i);
            float4 xb = __ldcs(v + i + RT);
            float4 xc = __ldcs(v + i + 2 * RT);
            float4 xd = __ldcs(v + i + 3 * RT);

            s0 += (__expf(xa.x) + __expf(xa.y)) + (__expf(xa.z) + __expf(xa.w));
            s1 += (__expf(xb.x) + __expf(xb.y)) + (__expf(xb.z) + __expf(xb.w));
            s2 += (__expf(xc.x) + __expf(xc.y)) + (__expf(xc.z) + __expf(xc.w));
            s3 += (__expf(xd.x) + __expf(xd.y)) + (__expf(xd.z) + __expf(xd.w));

            int ba = head + (i << 2);
            int bb = head + ((i + RT) << 2);
            int bc = head + ((i + 2 * RT) << 2);
            int bd = head + ((i + 3 * RT) << 2);

            m = fmaxf(m, (ba + 0 == t) ? -FLT_MAX : xa.x);
            m = fmaxf(m, (ba + 1 == t) ? -FLT_MAX : xa.y);
            m = fmaxf(m, (ba + 2 == t) ? -FLT_MAX : xa.z);
            m = fmaxf(m, (ba + 3 == t) ? -FLT_MAX : xa.w);
            m = fmaxf(m, (bb + 0 == t) ? -FLT_MAX : xb.x);
            m = fmaxf(m, (bb + 1 == t) ? -FLT_MAX : xb.y);
            m = fmaxf(m, (bb + 2 == t) ? -FLT_MAX : xb.z);
            m = fmaxf(m, (bb + 3 == t) ? -FLT_MAX : xb.w);
            m = fmaxf(m, (bc + 0 == t) ? -FLT_MAX : xc.x);
            m = fmaxf(m, (bc + 1 == t) ? -FLT_MAX : xc.y);
            m = fmaxf(m, (bc + 2 == t) ? -FLT_MAX : xc.z);
            m = fmaxf(m, (bc + 3 == t) ? -FLT_MAX : xc.w);
            m = fmaxf(m, (bd + 0 == t) ? -FLT_MAX : xd.x);
            m = fmaxf(m, (bd + 1 == t) ? -FLT_MAX : xd.y);
            m = fmaxf(m, (bd + 2 == t) ? -FLT_MAX : xd.z);
            m = fmaxf(m, (bd + 3 == t) ? -FLT_MAX : xd.w);
        }
        for (; i < nvec; i += RT) {
            float4 x = __ldcs(v + i);
            s0 += (__expf(x.x) + __expf(x.y)) + (__expf(x.z) + __expf(x.w));
            const int base = head + (i << 2);
            m = fmaxf(m, (base + 0 == t) ? -FLT_MAX : x.x);
            m = fmaxf(m, (base + 1 == t) ? -FLT_MAX : x.y);
            m = fmaxf(m, (base + 2 == t) ? -FLT_MAX : x.z);
            m = fmaxf(m, (base + 3 == t) ? -FLT_MAX : x.w);
        }
        if (tid == 0) {
            for (int j = 0; j < head; j++) {
                float x = row[j];
                s0 += __expf(x);
                m = fmaxf(m, (j == t) ? -FLT_MAX : x);
            }
            for (int j = tail_start; j < NC; j++) {
                float x = row[j];
                s0 += __expf(x);
                m = fmaxf(m, (j == t) ? -FLT_MAX : x);
            }
        }

        float s = (s0 + s1) + (s2 + s3);

        #pragma unroll
        for (int o = 16; o > 0; o >>= 1) {
            m = fmaxf(m, __shfl_down_sync(0xFFFFFFFFu, m, o));
            s += __shfl_down_sync(0xFFFFFFFFu, s, o);
        }
        if (lane == 0) { sh_a[wid] = m; sh_b[wid] = s; }
        __syncthreads();

        if (wid == 0) {
            m = (lane < 8) ? sh_a[lane] : -FLT_MAX;
            s = (lane < 8) ? sh_b[lane] : 0.0f;
            #pragma unroll
            for (int o = 4; o > 0; o >>= 1) {
                m = fmaxf(m, __shfl_down_sync(0xFFFFFFFFu, m, o));
                s += __shfl_down_sync(0xFFFFFFFFu, s, o);
            }
            if (lane == 0) {
                const float nmax = m;
                const float correct = __ldg(row + t);
                const float lse = logf(s);
                const float margin = correct - nmax;
                float l = (margin >= 0.0f) ? (1.0f - margin)
                                           : (1.0f - correct + lse);
                l = fmaxf(l, 0.0f);
                l_buf[b] = l;
                neg_buf[b] = (margin < 0.0f) ? 1 : 0;
            }
        }
    }

    // ─────────────── election: last block to finish runs finalize ─────────
    if (tid == 0) {
        __threadfence();   // make l_buf/neg_buf writes visible device-wide
        const unsigned r = atomicAdd(&g_done, 1u);
        sh_flag = (r == NB - 1u);
    }
    __syncthreads();
    if (!sh_flag) return;
    if (tid == 0) atomicExch(&g_done, 0u);   // reset for next graph replay
    __threadfence();

    // ─────────────── finalize: sort-free monotone binary search ───────────
    // keep is a prefix of sorted order; boundary test for cutoff v:
    //   S(v) <= threshold + 2 - C(v),  C/S = count/sum of l <= v.
    // Monotone in v; l >= 0 so float bits are order-isomorphic to uint.
    float lv[16];
    {
        const float4* v4 = (const float4*)l_buf;
        #pragma unroll
        for (int i = 0; i < 4; i++) {
            const float4 x = __ldcg(v4 + tid * 4 + i);
            lv[i * 4 + 0] = x.x;
            lv[i * 4 + 1] = x.y;
            lv[i * 4 + 2] = x.z;
            lv[i * 4 + 3] = x.w;
        }
    }
    int nn = 0;
    {
        const int4* n4 = (const int4*)neg_buf;
        #pragma unroll
        for (int i = 0; i < 4; i++) {
            const int4 x = __ldcg(n4 + tid * 4 + i);
            nn += (x.x + x.y) + (x.z + x.w);
        }
    }
    // joint reduction: n_neg, min(l), max(l)  → adaptive search range
    float mn = lv[0], mx = lv[0];
    #pragma unroll
    for (int i = 1; i < 16; i++) {
        mn = fminf(mn, lv[i]);
        mx = fmaxf(mx, lv[i]);
    }
    float nnf = (float)nn;
    #pragma unroll
    for (int o = 16; o > 0; o >>= 1) {
        nnf += __shfl_xor_sync(0xFFFFFFFFu, nnf, o);
        mn = fminf(mn, __shfl_xor_sync(0xFFFFFFFFu, mn, o));
        mx = fmaxf(mx, __shfl_xor_sync(0xFFFFFFFFu, mx, o));
    }
    if (lane == 0) { sh_a[wid] = mn; sh_b[wid] = mx; sh_c[wid] = nnf; }
    __syncthreads();
    mn = sh_a[0]; mx = sh_b[0]; nnf = 0.0f;
    #pragma unroll
    for (int w = 0; w < 8; w++) {
        mn = fminf(mn, sh_a[w]);
        mx = fmaxf(mx, sh_b[w]);
        nnf += sh_c[w];
    }
    __syncthreads();

    const float c0 = (float)((1.0 - 0.3) * (1.0 - 0.3) * (double)NB);
    const float threshold = floorf(c0 + 0.7f * nnf);
    const float th2 = threshold + 2.0f;

    unsigned lo = __float_as_uint(mn);
    lo = (lo == 0u) ? 0u : lo - 1u;           // predicate(lo) = true
    unsigned hi = __float_as_uint(mx);
    if (hi < lo) hi = lo;

    float ansC = 0.0f, ansS = 0.0f;

    #pragma unroll 1
    for (int it = 0; it < 34; it++) {
        const bool fin = (lo >= hi);
        const unsigned mid = fin ? lo : (lo + ((hi - lo + 1) >> 1));
        const float pivot = __uint_as_float(mid);

        float S0 = 0, S1 = 0, C0 = 0, C1 = 0;
        #pragma unroll
        for (int i = 0; i < 16; i += 2) {
            if (lv[i + 0] <= pivot) { S0 += lv[i + 0]; C0 += 1.0f; }
            if (lv[i + 1] <= pivot) { S1 += lv[i + 1]; C1 += 1.0f; }
        }
        float S = S0 + S1;
        float C = C0 + C1;
        #pragma unroll
        for (int o = 16; o > 0; o >>= 1) {
            S += __shfl_xor_sync(0xFFFFFFFFu, S, o);
            C += __shfl_xor_sync(0xFFFFFFFFu, C, o);
        }
        if (lane == 0) { sh_a[wid] = S; sh_b[wid] = C; }
        __syncthreads();
        S = 0.0f; C = 0.0f;
        #pragma unroll
        for (int w = 0; w < 8; w++) { S += sh_a[w]; C += sh_b[w]; }
        __syncthreads();   // protect smem reuse next iteration

        if (fin) { ansC = C; ansS = S; break; }
        if (S <= th2 - C) lo = mid; else hi = mid - 1;
    }

    if (tid == 0) {
        const float npcl1 = ansS;               // sum of kept l
        const float npcl2 = threshold - ansC;   // threshold - #kept
        out[0] = (npcl1 < npcl2) ? npcl2 : npcl1;
    }
}

extern "C" void kernel_launch(void* const* d_in, const int* in_sizes, int n_in,
                              void* d_out, int out_size)
{
    const float* logits = (const float*)d_in[0];
    const int* target = (const int*)d_in[1];
    float* out = (float*)d_out;

    float* l_buf;
    int* neg_buf;
    cudaGetSymbolAddress((void**)&l_buf, g_l);
    cudaGetSymbolAddress((void**)&neg_buf, g_neg);

    npc_fused_kernel<<<NB, RT>>>(logits, target, l_buf, neg_buf, out);
}